// round 16
// baseline (speedup 1.0000x reference)
#include <cuda_runtime.h>
#include <cuda_fp16.h>
#include <cstdint>

namespace {
constexpr int kF       = 50;
constexpr int kE       = 64;
constexpr int kD       = 128;
constexpr int kPairs   = 4;                      // b-pairs per CTA (8 b)
constexpr int kGrid    = 16384 / (2 * kPairs);   // 2048 CTAs
constexpr int kThreads = 128;                    // 4 warps: 2 warps per b
constexpr uint32_t kBufB = 8192;   // one X tile: 64 f-rows x 128B (64 fp16 e)
}

__device__ __forceinline__ uint32_t smem_u32(const void* p) {
    uint32_t a;
    asm("{ .reg .u64 t; cvta.to.shared.u64 t, %1; cvt.u32.u64 %0, t; }"
        : "=r"(a) : "l"(p));
    return a;
}

__device__ __forceinline__ uint32_t packh2(float lo, float hi) {
    __half2 h = __floats2half2_rn(lo, hi);
    return *reinterpret_cast<uint32_t*>(&h);
}

__device__ __forceinline__ void ldsm4t(uint32_t& r0, uint32_t& r1, uint32_t& r2,
                                       uint32_t& r3, uint32_t a) {
    asm volatile(
        "ldmatrix.sync.aligned.m8n8.x4.trans.shared.b16 {%0,%1,%2,%3}, [%4];"
        : "=r"(r0), "=r"(r1), "=r"(r2), "=r"(r3) : "r"(a));
}

__device__ __forceinline__ void mma16816(float d[4], const uint32_t a[4],
                                         uint32_t b0, uint32_t b1) {
    asm volatile(
        "mma.sync.aligned.m16n8k16.row.col.f32.f16.f16.f32 "
        "{%0,%1,%2,%3}, {%4,%5,%6,%7}, {%8,%9}, {%0,%1,%2,%3};"
        : "+f"(d[0]), "+f"(d[1]), "+f"(d[2]), "+f"(d[3])
        : "r"(a[0]), "r"(a[1]), "r"(a[2]), "r"(a[3]), "r"(b0), "r"(b1));
}

__global__ void __launch_bounds__(kThreads, 3)
InnerProduct_f16_kernel(const float* __restrict__ X,
                        const float* __restrict__ Th,
                        float* __restrict__ out) {
    __shared__ __align__(16) char xs[2 * 2 * kBufB];  // [stage][slot] tiles

    const int tid  = threadIdx.x;
    const int lane = tid & 31;
    const int warp = tid >> 5;
    const int g    = lane >> 2;          // 0..7
    const int q    = lane & 3;           // 0..3
    const int slot  = warp >> 1;         // which b of the pair (0/1)
    const int dbase = (warp & 1) << 6;   // 64 d-rows per warp, full 64 e

    // ---- Theta A-fragments (fp16) in registers, once. 4 m-tiles, 4 k-steps.
    // m16n8k16 A frag: a0:(row g, f 16s+2q,+1)  a1:(row g+8, same f)
    //                  a2:(row g, f 16s+2q+8,+1) a3:(row g+8, same f)
    // K padded 50 -> 64 with zeros (pad products are exactly 0).
    uint32_t af[4][4][4];
#pragma unroll
    for (int t = 0; t < 4; ++t)
#pragma unroll
        for (int s = 0; s < 4; ++s) {
            const int r0 = dbase + 16 * t + g;
            const int r1 = r0 + 8;
            const int f0 = 16 * s + 2 * q;
            const int f1 = f0 + 8;
            auto thv = [&](int d, int f) -> float {
                return (f < kF) ? Th[d * kF + f] : 0.f;
            };
            af[t][s][0] = packh2(thv(r0, f0), thv(r0, f0 + 1));
            af[t][s][1] = packh2(thv(r1, f0), thv(r1, f0 + 1));
            af[t][s][2] = packh2(thv(r0, f1), thv(r0, f1 + 1));
            af[t][s][3] = packh2(thv(r1, f1), thv(r1, f1 + 1));
        }

    const uint32_t sb = smem_u32(xs);
    const size_t bstart = (size_t)blockIdx.x * (2 * kPairs);

    // ---- Zero the f-padding rows (50..63) of all 4 buffers, once.
    // The loader only ever writes f < 50, so they stay zero.
    for (int i = tid; i < 4 * (64 - kF) * 32; i += kThreads) {
        const int buf = i / ((64 - kF) * 32);
        const int r   = i % ((64 - kF) * 32);
        reinterpret_cast<uint32_t*>(xs + buf * kBufB + kF * 128)[r] = 0;
    }

    // ---- Loader: tile stored VERBATIM as [f=64 rows][e=64 fp16], 128B rows,
    // SW128 XOR swizzle on the 16B unit. Task t (0..199): f = t>>2, eq = t&3
    // -> 4 coalesced LDG.128 (e = 16*eq..+15), pack 8 h2 (adjacent e),
    // 2 swizzled STS.128 (e-units eb = 2*eq, 2*eq+1).
    uint32_t v[2][2][8];  // [slot][task][h2] staging for the pair's 2 tiles

    auto ldg_cvt = [&](int b, uint32_t (*dst)[8]) {
        const float* src = X + (bstart + b) * (size_t)(kF * kE);
#pragma unroll
        for (int i = 0; i < 2; ++i) {
            const int t = tid + kThreads * i;
            if (t < 200) {
                const float* p = src + (t >> 2) * kE + (t & 3) * 16;
                const float4 a0 = *reinterpret_cast<const float4*>(p);
                const float4 a1 = *reinterpret_cast<const float4*>(p + 4);
                const float4 a2 = *reinterpret_cast<const float4*>(p + 8);
                const float4 a3 = *reinterpret_cast<const float4*>(p + 12);
                dst[i][0] = packh2(a0.x, a0.y);
                dst[i][1] = packh2(a0.z, a0.w);
                dst[i][2] = packh2(a1.x, a1.y);
                dst[i][3] = packh2(a1.z, a1.w);
                dst[i][4] = packh2(a2.x, a2.y);
                dst[i][5] = packh2(a2.z, a2.w);
                dst[i][6] = packh2(a3.x, a3.y);
                dst[i][7] = packh2(a3.z, a3.w);
            }
        }
    };
    auto sts_pair = [&](int stage) {
#pragma unroll
        for (int s2 = 0; s2 < 2; ++s2) {
            const uint32_t base =
                sb + (uint32_t)stage * (2 * kBufB) + (uint32_t)s2 * kBufB;
#pragma unroll
            for (int i = 0; i < 2; ++i) {
                const int t = tid + kThreads * i;
                if (t < 200) {
                    const uint32_t f   = (uint32_t)(t >> 2);
                    const uint32_t eb0 = (uint32_t)((t & 3) * 2);
                    const uint32_t o0 = f * 128u + ((eb0 ^ (f & 7u)) << 4);
                    const uint32_t o1 = f * 128u + (((eb0 + 1u) ^ (f & 7u)) << 4);
                    asm volatile("st.shared.v4.b32 [%0], {%1,%2,%3,%4};"
                                 :: "r"(base + o0), "r"(v[s2][i][0]),
                                    "r"(v[s2][i][1]), "r"(v[s2][i][2]),
                                    "r"(v[s2][i][3]) : "memory");
                    asm volatile("st.shared.v4.b32 [%0], {%1,%2,%3,%4};"
                                 :: "r"(base + o1), "r"(v[s2][i][4]),
                                    "r"(v[s2][i][5]), "r"(v[s2][i][6]),
                                    "r"(v[s2][i][7]) : "memory");
                }
            }
        }
    };

    // ---- ldmatrix.x4.trans lane geometry (R9-proven). Matrix j = lane/8,
    // row r = lane%8:
    //   m0=(f-lo8, e-lo8) m1=(f-hi8, e-lo8) m2=(f-lo8, e-hi8) m3=(f-hi8, e-hi8)
    // Lane address: f = 16s + (j&1)*8 + r, e-unit u = 2*nb + (j>>1),
    // swizzled off = f*128 + ((u ^ r) << 4)   [since f&7 == r].
    const int j   = lane >> 3;
    const int r8  = lane & 7;
    const uint32_t lrow = (uint32_t)(((j & 1) * 8 + r8) * 128);
    const uint32_t lu   = (uint32_t)(j >> 1);

    // ---- Prologue: pair0 staged+stored, pair1 staged ----
    ldg_cvt(0, v[0]);
    ldg_cvt(1, v[1]);
    sts_pair(0);
    ldg_cvt(2, v[0]);
    ldg_cvt(3, v[1]);
    __syncthreads();

#pragma unroll 1
    for (int it = 0; it < kPairs; ++it) {
        const uint32_t base =
            sb + (uint32_t)(it & 1) * (2 * kBufB) + (uint32_t)slot * kBufB;

        // Store next pair (data loaded last iter), prefetch pair after next.
        if (it + 1 < kPairs) sts_pair((it + 1) & 1);
        if (it + 2 < kPairs) {
            ldg_cvt(2 * (it + 2), v[0]);
            ldg_cvt(2 * (it + 2) + 1, v[1]);
        }

        // ---- proj[d,e] = sum_f Theta[d,f]*X[f,e], n-block at a time.
        // Each n-block's accumulators die immediately into the running
        // squared sums -> 32 live acc regs; each ldsm.x4 feeds 8 MMAs.
        float sum[4][2];
#pragma unroll
        for (int t = 0; t < 4; ++t) sum[t][0] = sum[t][1] = 0.f;

#pragma unroll
        for (int nb = 0; nb < 4; ++nb) {
            float acc[4][2][4];
#pragma unroll
            for (int t = 0; t < 4; ++t)
#pragma unroll
                for (int h = 0; h < 2; ++h)
#pragma unroll
                    for (int c = 0; c < 4; ++c) acc[t][h][c] = 0.f;

            const uint32_t u = 2u * (uint32_t)nb + lu;
            const uint32_t coff = (u ^ (uint32_t)r8) << 4;
#pragma unroll
            for (int s = 0; s < 4; ++s) {
                uint32_t b0, b1, b2, b3;
                ldsm4t(b0, b1, b2, b3, base + 2048u * (uint32_t)s + lrow + coff);
#pragma unroll
                for (int t = 0; t < 4; ++t) {
                    mma16816(acc[t][0], af[t][s], b0, b1);
                    mma16816(acc[t][1], af[t][s], b2, b3);
                }
            }

            // Square-reduce this n-block. C frag rows: c0,c1 -> row g;
            // c2,c3 -> row g+8 (e-position irrelevant, we sum over e).
#pragma unroll
            for (int t = 0; t < 4; ++t)
#pragma unroll
                for (int h = 0; h < 2; ++h) {
                    sum[t][0] = fmaf(acc[t][h][0], acc[t][h][0], sum[t][0]);
                    sum[t][0] = fmaf(acc[t][h][1], acc[t][h][1], sum[t][0]);
                    sum[t][1] = fmaf(acc[t][h][2], acc[t][h][2], sum[t][1]);
                    sum[t][1] = fmaf(acc[t][h][3], acc[t][h][3], sum[t][1]);
                }
        }

        // ---- Final quad reduction (e spread across the 4 lanes of a quad).
        float* op = out + (bstart + 2 * it + slot) * kD + dbase;
#pragma unroll
        for (int t = 0; t < 4; ++t) {
            float s0 = sum[t][0], s1 = sum[t][1];
            s0 += __shfl_xor_sync(0xffffffffu, s0, 1);
            s0 += __shfl_xor_sync(0xffffffffu, s0, 2);
            s1 += __shfl_xor_sync(0xffffffffu, s1, 1);
            s1 += __shfl_xor_sync(0xffffffffu, s1, 2);
            if (q == 0) {
                op[16 * t + g]     = s0;
                op[16 * t + g + 8] = s1;
            }
        }
        __syncthreads();
    }
}

extern "C" void kernel_launch(void* const* d_in, const int* in_sizes, int n_in,
                              void* d_out, int out_size) {
    const float* X  = (const float*)d_in[0];   // inputs [16384, 50, 64] fp32
    const float* Th = (const float*)d_in[1];   // Theta  [128, 50] fp32
    float* out      = (float*)d_out;           // [16384, 128] fp32
    (void)in_sizes; (void)n_in; (void)out_size;

    InnerProduct_f16_kernel<<<kGrid, kThreads>>>(X, Th, out);
}